// round 6
// baseline (speedup 1.0000x reference)
#include <cuda_runtime.h>
#include <cuda_bf16.h>

#define CW    32            // context window
#define DDIM  512           // embedding dim
#define NTHR  128           // 4 warps per CTA, one CTA per batch row
#define NW    4             // warps per CTA
#define CPW   (CW / NW)     // context rows per warp = 8

// Lane l owns dims { i*128 + l*4 .. +4 } for i in 0..3  (coalesced, conflict-free)

__device__ __forceinline__ float4 ldg_v4_nocse(const float4* p) {
    // Opaque reload: guaranteed L1-hot (same row just loaded), cannot be CSE'd
    // back into a live register by the compiler.
    float4 v;
    asm volatile("ld.global.nc.v4.f32 {%0,%1,%2,%3}, [%4];"
                 : "=f"(v.x), "=f"(v.y), "=f"(v.z), "=f"(v.w)
                 : "l"(p));
    return v;
}

__global__ __launch_bounds__(NTHR, 8)
void kre_kernel(const int* __restrict__ context,
                const int* __restrict__ center,
                const float* __restrict__ W,
                float* __restrict__ out)
{
    __shared__ float s_acc[NW * DDIM];   // per-warp partial outputs (8 KB)
    __shared__ float s_wsum[NW];
    __shared__ int   s_idx[CW];

    const int b    = blockIdx.x;
    const int tid  = threadIdx.x;
    const int lane = tid & 31;
    const int warp = tid >> 5;

    if (tid < CW) s_idx[tid] = context[b * CW + tid];
    __syncthreads();

    // Center row slice for this lane (kept in registers for all 8 rows)
    const float4* cen_p = (const float4*)(W + (size_t)center[b] * DDIM) + lane;
    float4 cen[4];
    #pragma unroll
    for (int i = 0; i < 4; ++i) cen[i] = cen_p[i * 32];

    float4 acc[4];
    #pragma unroll
    for (int i = 0; i < 4; ++i) acc[i] = make_float4(0.f, 0.f, 0.f, 0.f);
    float wsum = 0.f;

    // Each warp: 8 context rows. Per row: load -> dsq -> warp-reduce -> wgt,
    // then RELOAD the (L1-hot) row for the weighted accumulate. This keeps v
    // dead across the shuffle chain, cutting live registers so 8 CTAs/SM fit.
    #pragma unroll
    for (int cc = 0; cc < CPW; ++cc) {
        const float4* p = (const float4*)(W + (size_t)s_idx[warp * CPW + cc] * DDIM) + lane;

        float d = 0.f;
        #pragma unroll
        for (int i = 0; i < 4; ++i) {
            const float4 v = p[i * 32];
            const float dx = v.x - cen[i].x;
            const float dy = v.y - cen[i].y;
            const float dz = v.z - cen[i].z;
            const float dw = v.w - cen[i].w;
            d = fmaf(dx, dx, d);
            d = fmaf(dy, dy, d);
            d = fmaf(dz, dz, d);
            d = fmaf(dw, dw, d);
        }
        d += __shfl_xor_sync(0xffffffffu, d, 16);
        d += __shfl_xor_sync(0xffffffffu, d, 8);
        d += __shfl_xor_sync(0xffffffffu, d, 4);
        d += __shfl_xor_sync(0xffffffffu, d, 2);
        d += __shfl_xor_sync(0xffffffffu, d, 1);

        const float wgt = __expf(-0.5f * d);   // SIGMA = 1; exact 1.0 at d==0
        wsum += wgt;

        #pragma unroll
        for (int i = 0; i < 4; ++i) {
            const float4 v = ldg_v4_nocse(p + i * 32);   // L1 hit
            acc[i].x = fmaf(wgt, v.x, acc[i].x);
            acc[i].y = fmaf(wgt, v.y, acc[i].y);
            acc[i].z = fmaf(wgt, v.z, acc[i].z);
            acc[i].w = fmaf(wgt, v.w, acc[i].w);
        }
    }

    // Spill per-warp partials (lane stride 16 B -> conflict-free)
    #pragma unroll
    for (int i = 0; i < 4; ++i)
        *(float4*)(s_acc + warp * DDIM + i * 128 + lane * 4) = acc[i];
    if (lane == 0) s_wsum[warp] = wsum;   // wgt broadcast => wsum lane-uniform
    __syncthreads();

    // Combine 4 warp partials; normalize once at the end (same math as ref)
    const float inv = 1.0f / (s_wsum[0] + s_wsum[1] + s_wsum[2] + s_wsum[3] + 1e-8f);

    float4 r = make_float4(0.f, 0.f, 0.f, 0.f);
    #pragma unroll
    for (int w = 0; w < NW; ++w) {
        const float4 p = *(const float4*)(s_acc + w * DDIM + tid * 4);
        r.x += p.x; r.y += p.y; r.z += p.z; r.w += p.w;
    }
    r.x *= inv; r.y *= inv; r.z *= inv; r.w *= inv;
    // Streaming write-through: don't let the 16 MB output evict W from L2.
    __stwt((float4*)(out + (size_t)b * DDIM + tid * 4), r);
}

extern "C" void kernel_launch(void* const* d_in, const int* in_sizes, int n_in,
                              void* d_out, int out_size)
{
    const int*   context = (const int*)d_in[0];   // [B, C] int32
    const int*   center  = (const int*)d_in[1];   // [B]    int32
    const float* W       = (const float*)d_in[2]; // [V, D] float32
    float*       out     = (float*)d_out;         // [B, D] float32

    const int B = in_sizes[1];                    // 8192

    kre_kernel<<<B, NTHR>>>(context, center, W, out);
}